// round 13
// baseline (speedup 1.0000x reference)
#include <cuda_runtime.h>
#include <cuda_fp16.h>
#include <cstdint>

// Problem constants (match reference_code)
#define NN 50000
#define EE 800000
#define DD 64

// Fused prep kernel geometry: PB blocks x PT threads, all resident (PB <= 148)
#define PB 98
#define PT 512
#define NCHUNK (NN / 4)                 // 12500 row-quads (NN % 4 == 0)

// ----------------------------------------------------------------------------
// Scratch (device globals; no allocation allowed). BSS-zeroed at load; the
// prep kernel leaves g_deg and g_barrier zeroed at exit, so every graph
// replay sees identical initial state.
// ----------------------------------------------------------------------------
__device__ __half g_h[NN * DD];       // ping (fp16 inter-hop tensor)
__device__ __half g_t[NN * DD];       // pong
__device__ int    g_deg[NN];          // in-degree histogram (zero at entry/exit)
__device__ int    g_rowptr[NN + 1];   // CSR row pointers (by dst)
__device__ int    g_cursor[NN];       // scatter cursors
__device__ int    g_bsum[PB];         // per-tile scan sums
__device__ int    g_barrier;          // grid barrier counter (zero at entry/exit)
__device__ int2   g_csr[EE];          // packed {src, w_bits} per CSR slot

// Grid-wide barrier: all PB blocks resident -> spin is deadlock-free.
__device__ __forceinline__ void gbar(int phase) {
    __syncthreads();
    if (threadIdx.x == 0) {
        __threadfence();
        atomicAdd(&g_barrier, 1);
        while (*(volatile int*)&g_barrier < phase * PB) { __nanosleep(40); }
        __threadfence();
    }
    __syncthreads();
}

// ----------------------------------------------------------------------------
// Fused prep: P1 init(h=fp16(x), out=0.25x) + degree count; P2a tile scan;
// P2b finalize rowptr/cursor (+deg reset); P3 CSR scatter. One launch.
// ----------------------------------------------------------------------------
__global__ void __launch_bounds__(PT, 1)
prep_kernel(const float4* __restrict__ x4,
            float4* __restrict__ out4,
            const int4* __restrict__ src4,
            const int4* __restrict__ dst4,
            const float4* __restrict__ w4) {
    int tid = threadIdx.x;
    int b   = blockIdx.x;
    int gt  = b * PT + tid;
    int gstride = PB * PT;

    // ---- P1: init + count -------------------------------------------------
    {
        __half2* h2 = (__half2*)g_h;
        const int n4 = NN * DD / 4;
        for (int idx = gt; idx < n4; idx += gstride) {
            float4 v = x4[idx];
            h2[idx * 2 + 0] = __floats2half2_rn(v.x, v.y);
            h2[idx * 2 + 1] = __floats2half2_rn(v.z, v.w);
            out4[idx] = make_float4(0.25f * v.x, 0.25f * v.y, 0.25f * v.z, 0.25f * v.w);
        }
        for (int e = gt; e < EE / 4; e += gstride) {
            int4 d = dst4[e];
            atomicAdd(&g_deg[d.x], 1);
            atomicAdd(&g_deg[d.y], 1);
            atomicAdd(&g_deg[d.z], 1);
            atomicAdd(&g_deg[d.w], 1);
        }
    }
    gbar(1);

    // ---- P2a: per-tile inclusive scan (tile = PT elements) -----------------
    __shared__ int wsum[32];              // PT/32 = 16 used; padded to 32
    __shared__ int s_boff;
    int i = b * PT + tid;                 // tile b covers [b*PT, b*PT+PT)
    int lane = tid & 31, wid = tid >> 5;
    int v = (i < NN) ? g_deg[i] : 0;
    int s = v;
    #pragma unroll
    for (int off = 1; off < 32; off <<= 1) {
        int t = __shfl_up_sync(0xFFFFFFFF, s, off);
        if (lane >= off) s += t;
    }
    if (lane == 31) wsum[wid] = s;
    __syncthreads();
    if (wid == 0) {
        // ALL 32 lanes participate (lanes >= PT/32 contribute 0) — legal mask.
        int ws = (lane < PT / 32) ? wsum[lane] : 0;
        #pragma unroll
        for (int off = 1; off < 32; off <<= 1) {
            int t = __shfl_up_sync(0xFFFFFFFF, ws, off);
            if (lane >= off) ws += t;
        }
        wsum[lane] = ws;
    }
    __syncthreads();
    int incl = s + (wid > 0 ? wsum[wid - 1] : 0);
    if (tid == PT - 1) g_bsum[b] = incl;
    gbar(2);

    // ---- P2b: block offset (warp-parallel over <=PB-1 sums) + finalize -----
    if (tid < 32) {
        int acc = 0;
        for (int j = tid; j < b; j += 32) acc += g_bsum[j];
        #pragma unroll
        for (int o = 16; o > 0; o >>= 1) acc += __shfl_down_sync(0xFFFFFFFF, acc, o);
        if (tid == 0) s_boff = acc;
    }
    __syncthreads();
    if (i < NN) {
        int e = incl + s_boff;
        g_rowptr[i + 1] = e;
        g_cursor[i] = e - v;
        g_deg[i] = 0;                     // reset for next replay
    }
    if (b == 0 && tid == 0) g_rowptr[0] = 0;
    gbar(3);

    // ---- P3: CSR scatter (4 edges/thread-step, 8B packed stores) -----------
    for (int e = gt; e < EE / 4; e += gstride) {
        int4   sv = src4[e];
        int4   dv = dst4[e];
        float4 wv = w4[e];
        int p0 = atomicAdd(&g_cursor[dv.x], 1);
        int p1 = atomicAdd(&g_cursor[dv.y], 1);
        int p2 = atomicAdd(&g_cursor[dv.z], 1);
        int p3 = atomicAdd(&g_cursor[dv.w], 1);
        g_csr[p0] = make_int2(sv.x, __float_as_int(wv.x));
        g_csr[p1] = make_int2(sv.y, __float_as_int(wv.y));
        g_csr[p2] = make_int2(sv.z, __float_as_int(wv.z));
        g_csr[p3] = make_int2(sv.w, __float_as_int(wv.w));
    }

    // ---- final arrive: last block resets the barrier counter ---------------
    __syncthreads();
    if (tid == 0) {
        __threadfence();
        int old = atomicAdd(&g_barrier, 1);
        if (old == 4 * PB - 1) *(volatile int*)&g_barrier = 0;
    }
}

// ----------------------------------------------------------------------------
// SpMM hop: quarter-warp per dst row (8 lanes x uint4 = one 128B fp16 row).
// 8-deep unrolled load block (16 independent LDGs in flight per warp) before
// the math block -> high MLP; persistent static-stride grid, 4 blocks/SM.
// fp32 accumulation.
// ----------------------------------------------------------------------------
__device__ __forceinline__ void acc8(float* a, float w, const uint4& p) {
    float2 f0 = __half22float2(*(const __half2*)&p.x);
    float2 f1 = __half22float2(*(const __half2*)&p.y);
    float2 f2 = __half22float2(*(const __half2*)&p.z);
    float2 f3 = __half22float2(*(const __half2*)&p.w);
    a[0] += w * f0.x; a[1] += w * f0.y;
    a[2] += w * f1.x; a[3] += w * f1.y;
    a[4] += w * f2.x; a[5] += w * f2.y;
    a[6] += w * f3.x; a[7] += w * f3.y;
}

template <bool LAST>
__global__ void __launch_bounds__(256, 4)
spmm_kernel(const __half* __restrict__ h,
            __half* __restrict__ hout,
            float* __restrict__ out) {
    const uint4* __restrict__ h8 = (const uint4*)h;   // 8 halves per uint4
    int wid   = threadIdx.x >> 5;
    int warp  = blockIdx.x * (blockDim.x >> 5) + wid;
    int nwarp = gridDim.x * (blockDim.x >> 5);
    int lane  = threadIdx.x & 31;
    int q     = lane >> 3;
    int flane = lane & 7;

    for (int c = warp; c < NCHUNK; c += nwarp) {
        int row = c * 4 + q;                    // NN % 4 == 0: always < NN

        int beg = g_rowptr[row];
        int end = g_rowptr[row + 1];

        float a[8] = {0.f, 0.f, 0.f, 0.f, 0.f, 0.f, 0.f, 0.f};

        int j = beg;
        for (; j + 7 < end; j += 8) {
            int2 e0 = __ldg(&g_csr[j]);
            int2 e1 = __ldg(&g_csr[j + 1]);
            int2 e2 = __ldg(&g_csr[j + 2]);
            int2 e3 = __ldg(&g_csr[j + 3]);
            int2 e4 = __ldg(&g_csr[j + 4]);
            int2 e5 = __ldg(&g_csr[j + 5]);
            int2 e6 = __ldg(&g_csr[j + 6]);
            int2 e7 = __ldg(&g_csr[j + 7]);
            uint4 p0 = __ldg(&h8[e0.x * 8 + flane]);
            uint4 p1 = __ldg(&h8[e1.x * 8 + flane]);
            uint4 p2 = __ldg(&h8[e2.x * 8 + flane]);
            uint4 p3 = __ldg(&h8[e3.x * 8 + flane]);
            uint4 p4 = __ldg(&h8[e4.x * 8 + flane]);
            uint4 p5 = __ldg(&h8[e5.x * 8 + flane]);
            uint4 p6 = __ldg(&h8[e6.x * 8 + flane]);
            uint4 p7 = __ldg(&h8[e7.x * 8 + flane]);
            acc8(a, __int_as_float(e0.y), p0);
            acc8(a, __int_as_float(e1.y), p1);
            acc8(a, __int_as_float(e2.y), p2);
            acc8(a, __int_as_float(e3.y), p3);
            acc8(a, __int_as_float(e4.y), p4);
            acc8(a, __int_as_float(e5.y), p5);
            acc8(a, __int_as_float(e6.y), p6);
            acc8(a, __int_as_float(e7.y), p7);
        }
        for (; j < end; j++) {
            int2 e = __ldg(&g_csr[j]);
            uint4 p = __ldg(&h8[e.x * 8 + flane]);
            acc8(a, __int_as_float(e.y), p);
        }

        if (!LAST) {
            uint4 packed;
            *(__half2*)&packed.x = __floats2half2_rn(a[0], a[1]);
            *(__half2*)&packed.y = __floats2half2_rn(a[2], a[3]);
            *(__half2*)&packed.z = __floats2half2_rn(a[4], a[5]);
            *(__half2*)&packed.w = __floats2half2_rn(a[6], a[7]);
            ((uint4*)hout)[row * 8 + flane] = packed;
        }

        float4* o = (float4*)out + row * 16 + flane * 2;
        float4 o0 = o[0], o1 = o[1];
        o0.x += 0.25f * a[0]; o0.y += 0.25f * a[1];
        o0.z += 0.25f * a[2]; o0.w += 0.25f * a[3];
        o1.x += 0.25f * a[4]; o1.y += 0.25f * a[5];
        o1.z += 0.25f * a[6]; o1.w += 0.25f * a[7];
        o[0] = o0; o[1] = o1;
    }
}

// ----------------------------------------------------------------------------
// launch (4 kernels total)
// ----------------------------------------------------------------------------
extern "C" void kernel_launch(void* const* d_in, const int* in_sizes, int n_in,
                              void* d_out, int out_size) {
    const float* x   = (const float*)d_in[0];
    const float* w   = (const float*)d_in[1];
    const int*   src = (const int*)d_in[2];
    const int*   dst = (const int*)d_in[3];
    float*       out = (float*)d_out;

    (void)in_sizes; (void)n_in; (void)out_size;

    __half* hA; __half* hB;
    cudaGetSymbolAddress((void**)&hA, g_h);
    cudaGetSymbolAddress((void**)&hB, g_t);

    // 1) fused prep: init + count + scan + fill (grid-sync phases, 1 launch)
    prep_kernel<<<PB, PT>>>((const float4*)x, (float4*)out,
                            (const int4*)src, (const int4*)dst, (const float4*)w);

    // 2-4) K=3 hops, persistent grid (4 blocks/SM), 8-deep unrolled gathers,
    //      ping-pong fp16 buffers, fused residual (+0.25*h) into out
    dim3 blk(256);
    dim3 grd(148 * 4);
    spmm_kernel<false><<<grd, blk>>>(hA, hB, out);   // hop 1: x    -> g_t
    spmm_kernel<false><<<grd, blk>>>(hB, hA, out);   // hop 2: g_t  -> g_h
    spmm_kernel<true ><<<grd, blk>>>(hA, hB, out);   // hop 3: residual only
}

// round 14
// speedup vs baseline: 1.1486x; 1.1486x over previous
#include <cuda_runtime.h>
#include <cuda_fp16.h>
#include <cstdint>

// Problem constants (match reference_code)
#define NN 50000
#define EE 800000
#define DD 64

// Fused prep kernel geometry: PB blocks x PT threads, all resident (PB <= 148)
#define PB 98
#define PT 512

// ----------------------------------------------------------------------------
// Scratch (device globals; no allocation allowed). BSS-zeroed at load; the
// prep kernel leaves g_deg and g_barrier zeroed at exit, so every graph
// replay sees identical initial state.
// ----------------------------------------------------------------------------
__device__ __half g_h[NN * DD];       // ping (fp16 inter-hop tensor)
__device__ __half g_t[NN * DD];       // pong
__device__ int    g_deg[NN];          // in-degree histogram (zero at entry/exit)
__device__ int    g_rowptr[NN + 1];   // CSR row pointers (by dst)
__device__ int    g_cursor[NN];       // scatter cursors
__device__ int    g_bsum[PB];         // per-tile scan sums
__device__ int    g_barrier;          // grid barrier counter (zero at entry/exit)
__device__ int2   g_csr[EE];          // packed {src, w_bits} per CSR slot

// Grid-wide barrier: all PB blocks resident -> spin is deadlock-free.
__device__ __forceinline__ void gbar(int phase) {
    __syncthreads();
    if (threadIdx.x == 0) {
        __threadfence();
        atomicAdd(&g_barrier, 1);
        while (*(volatile int*)&g_barrier < phase * PB) { __nanosleep(40); }
        __threadfence();
    }
    __syncthreads();
}

// ----------------------------------------------------------------------------
// Fused prep: P1 init(h=fp16(x), out=0.25x) + degree count; P2a tile scan;
// P2b finalize rowptr/cursor (+deg reset); P3 CSR scatter. One launch.
// ----------------------------------------------------------------------------
__global__ void __launch_bounds__(PT, 1)
prep_kernel(const float4* __restrict__ x4,
            float4* __restrict__ out4,
            const int4* __restrict__ src4,
            const int4* __restrict__ dst4,
            const float4* __restrict__ w4) {
    int tid = threadIdx.x;
    int b   = blockIdx.x;
    int gt  = b * PT + tid;
    int gstride = PB * PT;

    // ---- P1: init + count -------------------------------------------------
    {
        __half2* h2 = (__half2*)g_h;
        const int n4 = NN * DD / 4;
        for (int idx = gt; idx < n4; idx += gstride) {
            float4 v = x4[idx];
            h2[idx * 2 + 0] = __floats2half2_rn(v.x, v.y);
            h2[idx * 2 + 1] = __floats2half2_rn(v.z, v.w);
            out4[idx] = make_float4(0.25f * v.x, 0.25f * v.y, 0.25f * v.z, 0.25f * v.w);
        }
        for (int e = gt; e < EE / 4; e += gstride) {
            int4 d = dst4[e];
            atomicAdd(&g_deg[d.x], 1);
            atomicAdd(&g_deg[d.y], 1);
            atomicAdd(&g_deg[d.z], 1);
            atomicAdd(&g_deg[d.w], 1);
        }
    }
    gbar(1);

    // ---- P2a: per-tile inclusive scan (tile = PT elements) -----------------
    __shared__ int wsum[32];              // PT/32 = 16 used; padded to 32
    __shared__ int s_boff;
    int i = b * PT + tid;                 // tile b covers [b*PT, b*PT+PT)
    int lane = tid & 31, wid = tid >> 5;
    int v = (i < NN) ? g_deg[i] : 0;
    int s = v;
    #pragma unroll
    for (int off = 1; off < 32; off <<= 1) {
        int t = __shfl_up_sync(0xFFFFFFFF, s, off);
        if (lane >= off) s += t;
    }
    if (lane == 31) wsum[wid] = s;
    __syncthreads();
    if (wid == 0) {
        // ALL 32 lanes participate (lanes >= PT/32 contribute 0) — legal mask.
        int ws = (lane < PT / 32) ? wsum[lane] : 0;
        #pragma unroll
        for (int off = 1; off < 32; off <<= 1) {
            int t = __shfl_up_sync(0xFFFFFFFF, ws, off);
            if (lane >= off) ws += t;
        }
        wsum[lane] = ws;
    }
    __syncthreads();
    int incl = s + (wid > 0 ? wsum[wid - 1] : 0);
    if (tid == PT - 1) g_bsum[b] = incl;
    gbar(2);

    // ---- P2b: block offset (warp-parallel over <=PB-1 sums) + finalize -----
    if (tid < 32) {
        int acc = 0;
        for (int j = tid; j < b; j += 32) acc += g_bsum[j];
        #pragma unroll
        for (int o = 16; o > 0; o >>= 1) acc += __shfl_down_sync(0xFFFFFFFF, acc, o);
        if (tid == 0) s_boff = acc;
    }
    __syncthreads();
    if (i < NN) {
        int e = incl + s_boff;
        g_rowptr[i + 1] = e;
        g_cursor[i] = e - v;
        g_deg[i] = 0;                     // reset for next replay
    }
    if (b == 0 && tid == 0) g_rowptr[0] = 0;
    gbar(3);

    // ---- P3: CSR scatter (4 edges/thread-step, 8B packed stores) -----------
    for (int e = gt; e < EE / 4; e += gstride) {
        int4   sv = src4[e];
        int4   dv = dst4[e];
        float4 wv = w4[e];
        int p0 = atomicAdd(&g_cursor[dv.x], 1);
        int p1 = atomicAdd(&g_cursor[dv.y], 1);
        int p2 = atomicAdd(&g_cursor[dv.z], 1);
        int p3 = atomicAdd(&g_cursor[dv.w], 1);
        g_csr[p0] = make_int2(sv.x, __float_as_int(wv.x));
        g_csr[p1] = make_int2(sv.y, __float_as_int(wv.y));
        g_csr[p2] = make_int2(sv.z, __float_as_int(wv.z));
        g_csr[p3] = make_int2(sv.w, __float_as_int(wv.w));
    }

    // ---- final arrive: last block resets the barrier counter ---------------
    __syncthreads();
    if (tid == 0) {
        __threadfence();
        int old = atomicAdd(&g_barrier, 1);
        if (old == 4 * PB - 1) *(volatile int*)&g_barrier = 0;
    }
}

// ----------------------------------------------------------------------------
// SpMM hop: FULL warp per dst row. Lane holds one half2 (2 features); the
// gather h[src] is one LDG.32 covering exactly one 128B line (1 wavefront).
// Edges are loaded cooperatively (one coalesced LDG serves 32 edges) and
// shfl-broadcast. ~6.8 warp-inst and ~1.1 L1 wavefronts per edge.
// fp32 accumulation; persistent grid, 8 blocks/SM.
// ----------------------------------------------------------------------------
template <bool LAST>
__global__ void __launch_bounds__(256, 8)
spmm_kernel(const __half* __restrict__ h,
            __half* __restrict__ hout,
            float* __restrict__ out) {
    const unsigned* __restrict__ hw = (const unsigned*)h;   // half2 per lane
    int warp  = blockIdx.x * (blockDim.x >> 5) + (threadIdx.x >> 5);
    int nwarp = gridDim.x * (blockDim.x >> 5);
    int lane  = threadIdx.x & 31;

    for (int row = warp; row < NN; row += nwarp) {
        int beg = g_rowptr[row];
        int end = g_rowptr[row + 1];

        float2 a0 = make_float2(0.f, 0.f);
        float2 a1 = make_float2(0.f, 0.f);

        for (int cb = beg; cb < end; cb += 32) {
            int cnt = end - cb; if (cnt > 32) cnt = 32;
            // cooperative edge load: lane L holds edge cb+L (coalesced)
            int2 ev = make_int2(0, 0);
            if (cb + lane < end) ev = __ldg(&g_csr[cb + lane]);

            int k = 0;
            for (; k + 3 < cnt; k += 4) {
                int s0 = __shfl_sync(0xFFFFFFFF, ev.x, k);
                int b0 = __shfl_sync(0xFFFFFFFF, ev.y, k);
                int s1 = __shfl_sync(0xFFFFFFFF, ev.x, k + 1);
                int b1 = __shfl_sync(0xFFFFFFFF, ev.y, k + 1);
                int s2 = __shfl_sync(0xFFFFFFFF, ev.x, k + 2);
                int b2 = __shfl_sync(0xFFFFFFFF, ev.y, k + 2);
                int s3 = __shfl_sync(0xFFFFFFFF, ev.x, k + 3);
                int b3 = __shfl_sync(0xFFFFFFFF, ev.y, k + 3);
                unsigned p0 = __ldg(&hw[s0 * 32 + lane]);
                unsigned p1 = __ldg(&hw[s1 * 32 + lane]);
                unsigned p2 = __ldg(&hw[s2 * 32 + lane]);
                unsigned p3 = __ldg(&hw[s3 * 32 + lane]);
                float2 f0 = __half22float2(*(__half2*)&p0);
                float2 f1 = __half22float2(*(__half2*)&p1);
                float2 f2 = __half22float2(*(__half2*)&p2);
                float2 f3 = __half22float2(*(__half2*)&p3);
                float w0 = __int_as_float(b0), w1 = __int_as_float(b1);
                float w2 = __int_as_float(b2), w3 = __int_as_float(b3);
                a0.x += w0 * f0.x; a0.y += w0 * f0.y;
                a1.x += w1 * f1.x; a1.y += w1 * f1.y;
                a0.x += w2 * f2.x; a0.y += w2 * f2.y;
                a1.x += w3 * f3.x; a1.y += w3 * f3.y;
            }
            for (; k < cnt; k++) {
                int s0 = __shfl_sync(0xFFFFFFFF, ev.x, k);
                int b0 = __shfl_sync(0xFFFFFFFF, ev.y, k);
                unsigned p0 = __ldg(&hw[s0 * 32 + lane]);
                float2 f0 = __half22float2(*(__half2*)&p0);
                float w0 = __int_as_float(b0);
                a0.x += w0 * f0.x; a0.y += w0 * f0.y;
            }
        }

        float2 acc = make_float2(a0.x + a1.x, a0.y + a1.y);

        int idx = row * 32 + lane;
        if (!LAST) {
            __half2 ph = __floats2half2_rn(acc.x, acc.y);
            ((unsigned*)hout)[idx] = *(unsigned*)&ph;
        }
        float2* o = (float2*)out + idx;
        float2 ov = *o;
        ov.x += 0.25f * acc.x;
        ov.y += 0.25f * acc.y;
        *o = ov;
    }
}

// ----------------------------------------------------------------------------
// launch (4 kernels total)
// ----------------------------------------------------------------------------
extern "C" void kernel_launch(void* const* d_in, const int* in_sizes, int n_in,
                              void* d_out, int out_size) {
    const float* x   = (const float*)d_in[0];
    const float* w   = (const float*)d_in[1];
    const int*   src = (const int*)d_in[2];
    const int*   dst = (const int*)d_in[3];
    float*       out = (float*)d_out;

    (void)in_sizes; (void)n_in; (void)out_size;

    __half* hA; __half* hB;
    cudaGetSymbolAddress((void**)&hA, g_h);
    cudaGetSymbolAddress((void**)&hB, g_t);

    // 1) fused prep: init + count + scan + fill (grid-sync phases, 1 launch)
    prep_kernel<<<PB, PT>>>((const float4*)x, (float4*)out,
                            (const int4*)src, (const int4*)dst, (const float4*)w);

    // 2-4) K=3 hops, persistent grid (8 blocks/SM), full-warp rows with
    //      cooperative edge broadcast, ping-pong fp16 buffers, fused residual
    dim3 blk(256);
    dim3 grd(148 * 8);
    spmm_kernel<false><<<grd, blk>>>(hA, hB, out);   // hop 1: x    -> g_t
    spmm_kernel<false><<<grd, blk>>>(hB, hA, out);   // hop 2: g_t  -> g_h
    spmm_kernel<true ><<<grd, blk>>>(hA, hB, out);   // hop 3: residual only
}

// round 15
// speedup vs baseline: 1.4696x; 1.2794x over previous
#include <cuda_runtime.h>
#include <cuda_fp16.h>
#include <cstdint>

// Problem constants (match reference_code)
#define NN 50000
#define EE 800000
#define DD 64

// Fused prep kernel geometry: PB blocks x PT threads, all resident (PB <= 148)
#define PB 98
#define PT 512
#define NCHUNK (NN / 4)                 // 12500 row-quads (NN % 4 == 0)

// ----------------------------------------------------------------------------
// Scratch (device globals; no allocation allowed). BSS-zeroed at load; the
// prep kernel leaves g_deg and g_barrier zeroed at exit, so every graph
// replay sees identical initial state.
// ----------------------------------------------------------------------------
__device__ __half g_h[NN * DD];       // ping (fp16 inter-hop tensor)
__device__ __half g_t[NN * DD];       // pong
__device__ int    g_deg[NN];          // in-degree histogram (zero at entry/exit)
__device__ int    g_rowptr[NN + 1];   // CSR row pointers (by dst)
__device__ int    g_cursor[NN];       // scatter cursors
__device__ int    g_bsum[PB];         // per-tile scan sums
__device__ int    g_barrier;          // grid barrier counter (zero at entry/exit)
__device__ int2   g_csr[EE];          // packed {src, w_bits} per CSR slot

// Grid-wide barrier: all PB blocks resident -> spin is deadlock-free.
__device__ __forceinline__ void gbar(int phase) {
    __syncthreads();
    if (threadIdx.x == 0) {
        __threadfence();
        atomicAdd(&g_barrier, 1);
        while (*(volatile int*)&g_barrier < phase * PB) { __nanosleep(40); }
        __threadfence();
    }
    __syncthreads();
}

// ----------------------------------------------------------------------------
// Fused prep: P1 init(h=fp16(x)) + degree count; P2a tile scan; P2b finalize
// rowptr/cursor (+deg reset); P3 CSR scatter. One launch. (out is written by
// the last hop now — no 0.25x pass here.)
// ----------------------------------------------------------------------------
__global__ void __launch_bounds__(PT, 1)
prep_kernel(const float4* __restrict__ x4,
            const int4* __restrict__ src4,
            const int4* __restrict__ dst4,
            const float4* __restrict__ w4) {
    int tid = threadIdx.x;
    int b   = blockIdx.x;
    int gt  = b * PT + tid;
    int gstride = PB * PT;

    // ---- P1: init + count -------------------------------------------------
    {
        __half2* h2 = (__half2*)g_h;
        const int n4 = NN * DD / 4;
        for (int idx = gt; idx < n4; idx += gstride) {
            float4 v = x4[idx];
            h2[idx * 2 + 0] = __floats2half2_rn(v.x, v.y);
            h2[idx * 2 + 1] = __floats2half2_rn(v.z, v.w);
        }
        for (int e = gt; e < EE / 4; e += gstride) {
            int4 d = dst4[e];
            atomicAdd(&g_deg[d.x], 1);
            atomicAdd(&g_deg[d.y], 1);
            atomicAdd(&g_deg[d.z], 1);
            atomicAdd(&g_deg[d.w], 1);
        }
    }
    gbar(1);

    // ---- P2a: per-tile inclusive scan (tile = PT elements) -----------------
    __shared__ int wsum[32];              // PT/32 = 16 used; padded to 32
    __shared__ int s_boff;
    int i = b * PT + tid;                 // tile b covers [b*PT, b*PT+PT)
    int lane = tid & 31, wid = tid >> 5;
    int v = (i < NN) ? g_deg[i] : 0;
    int s = v;
    #pragma unroll
    for (int off = 1; off < 32; off <<= 1) {
        int t = __shfl_up_sync(0xFFFFFFFF, s, off);
        if (lane >= off) s += t;
    }
    if (lane == 31) wsum[wid] = s;
    __syncthreads();
    if (wid == 0) {
        // ALL 32 lanes participate (lanes >= PT/32 contribute 0) — legal mask.
        int ws = (lane < PT / 32) ? wsum[lane] : 0;
        #pragma unroll
        for (int off = 1; off < 32; off <<= 1) {
            int t = __shfl_up_sync(0xFFFFFFFF, ws, off);
            if (lane >= off) ws += t;
        }
        wsum[lane] = ws;
    }
    __syncthreads();
    int incl = s + (wid > 0 ? wsum[wid - 1] : 0);
    if (tid == PT - 1) g_bsum[b] = incl;
    gbar(2);

    // ---- P2b: block offset (warp-parallel over <=PB-1 sums) + finalize -----
    if (tid < 32) {
        int acc = 0;
        for (int j = tid; j < b; j += 32) acc += g_bsum[j];
        #pragma unroll
        for (int o = 16; o > 0; o >>= 1) acc += __shfl_down_sync(0xFFFFFFFF, acc, o);
        if (tid == 0) s_boff = acc;
    }
    __syncthreads();
    if (i < NN) {
        int e = incl + s_boff;
        g_rowptr[i + 1] = e;
        g_cursor[i] = e - v;
        g_deg[i] = 0;                     // reset for next replay
    }
    if (b == 0 && tid == 0) g_rowptr[0] = 0;
    gbar(3);

    // ---- P3: CSR scatter (4 edges/thread-step, 8B packed stores) -----------
    for (int e = gt; e < EE / 4; e += gstride) {
        int4   sv = src4[e];
        int4   dv = dst4[e];
        float4 wv = w4[e];
        int p0 = atomicAdd(&g_cursor[dv.x], 1);
        int p1 = atomicAdd(&g_cursor[dv.y], 1);
        int p2 = atomicAdd(&g_cursor[dv.z], 1);
        int p3 = atomicAdd(&g_cursor[dv.w], 1);
        g_csr[p0] = make_int2(sv.x, __float_as_int(wv.x));
        g_csr[p1] = make_int2(sv.y, __float_as_int(wv.y));
        g_csr[p2] = make_int2(sv.z, __float_as_int(wv.z));
        g_csr[p3] = make_int2(sv.w, __float_as_int(wv.w));
    }

    // ---- final arrive: last block resets the barrier counter ---------------
    __syncthreads();
    if (tid == 0) {
        __threadfence();
        int old = atomicAdd(&g_barrier, 1);
        if (old == 4 * PB - 1) *(volatile int*)&g_barrier = 0;
    }
}

// ----------------------------------------------------------------------------
// Shared gather body (R11 core): quarter-warp per dst row, 8 lanes x uint4 =
// one 128B fp16 row per gather, 4-deep unroll. fp32 accumulation.
// ----------------------------------------------------------------------------
__device__ __forceinline__ void acc8(float* a, float w, const uint4& p) {
    float2 f0 = __half22float2(*(const __half2*)&p.x);
    float2 f1 = __half22float2(*(const __half2*)&p.y);
    float2 f2 = __half22float2(*(const __half2*)&p.z);
    float2 f3 = __half22float2(*(const __half2*)&p.w);
    a[0] += w * f0.x; a[1] += w * f0.y;
    a[2] += w * f1.x; a[3] += w * f1.y;
    a[4] += w * f2.x; a[5] += w * f2.y;
    a[6] += w * f3.x; a[7] += w * f3.y;
}

__device__ __forceinline__ void gather_row(const uint4* __restrict__ h8,
                                           int beg, int end, int flane,
                                           float* a) {
    int j = beg;
    for (; j + 3 < end; j += 4) {
        int2 e0 = __ldg(&g_csr[j]);
        int2 e1 = __ldg(&g_csr[j + 1]);
        int2 e2 = __ldg(&g_csr[j + 2]);
        int2 e3 = __ldg(&g_csr[j + 3]);
        uint4 p0 = __ldg(&h8[e0.x * 8 + flane]);
        uint4 p1 = __ldg(&h8[e1.x * 8 + flane]);
        uint4 p2 = __ldg(&h8[e2.x * 8 + flane]);
        uint4 p3 = __ldg(&h8[e3.x * 8 + flane]);
        acc8(a, __int_as_float(e0.y), p0);
        acc8(a, __int_as_float(e1.y), p1);
        acc8(a, __int_as_float(e2.y), p2);
        acc8(a, __int_as_float(e3.y), p3);
    }
    for (; j < end; j++) {
        int2 e = __ldg(&g_csr[j]);
        uint4 p = __ldg(&h8[e.x * 8 + flane]);
        acc8(a, __int_as_float(e.y), p);
    }
}

// ----------------------------------------------------------------------------
// Mid hop (1,2): hout[row] = fp16(sum_e w_e * h[src_e]); no out access.
// ----------------------------------------------------------------------------
__global__ void __launch_bounds__(256, 6)
spmm_mid_kernel(const __half* __restrict__ h,
                __half* __restrict__ hout) {
    const uint4* __restrict__ h8 = (const uint4*)h;
    int warp  = blockIdx.x * (blockDim.x >> 5) + (threadIdx.x >> 5);
    int nwarp = gridDim.x * (blockDim.x >> 5);
    int lane  = threadIdx.x & 31;
    int q     = lane >> 3;
    int flane = lane & 7;

    for (int c = warp; c < NCHUNK; c += nwarp) {
        int row = c * 4 + q;
        int beg = g_rowptr[row];
        int end = g_rowptr[row + 1];

        float a[8] = {0.f, 0.f, 0.f, 0.f, 0.f, 0.f, 0.f, 0.f};
        gather_row(h8, beg, end, flane, a);

        uint4 packed;
        *(__half2*)&packed.x = __floats2half2_rn(a[0], a[1]);
        *(__half2*)&packed.y = __floats2half2_rn(a[2], a[3]);
        *(__half2*)&packed.z = __floats2half2_rn(a[4], a[5]);
        *(__half2*)&packed.w = __floats2half2_rn(a[6], a[7]);
        ((uint4*)hout)[row * 8 + flane] = packed;
    }
}

// ----------------------------------------------------------------------------
// Last hop: h3 = A*h2 (gather from h2); out = 0.25*(x + h1 + h2 + h3).
// h1 = g_t, h2 = g_h (also the gather source), x = original fp32 input.
// ----------------------------------------------------------------------------
__global__ void __launch_bounds__(256, 6)
spmm_last_kernel(const __half* __restrict__ h2buf,
                 const __half* __restrict__ h1buf,
                 const float* __restrict__ x,
                 float* __restrict__ out) {
    const uint4* __restrict__ h8 = (const uint4*)h2buf;
    int warp  = blockIdx.x * (blockDim.x >> 5) + (threadIdx.x >> 5);
    int nwarp = gridDim.x * (blockDim.x >> 5);
    int lane  = threadIdx.x & 31;
    int q     = lane >> 3;
    int flane = lane & 7;

    for (int c = warp; c < NCHUNK; c += nwarp) {
        int row = c * 4 + q;
        int beg = g_rowptr[row];
        int end = g_rowptr[row + 1];

        float a[8] = {0.f, 0.f, 0.f, 0.f, 0.f, 0.f, 0.f, 0.f};
        gather_row(h8, beg, end, flane, a);   // a = h3[row] slice

        // combine: out = 0.25*(x + h1 + h2 + h3) for this 8-float slice
        int hidx = row * 8 + flane;           // uint4 index into fp16 buffers
        uint4 h1p = __ldg(&((const uint4*)h1buf)[hidx]);
        uint4 h2p = __ldg(&((const uint4*)h2buf)[hidx]);
        float2 h1f[4] = { __half22float2(*(__half2*)&h1p.x),
                          __half22float2(*(__half2*)&h1p.y),
                          __half22float2(*(__half2*)&h1p.z),
                          __half22float2(*(__half2*)&h1p.w) };
        float2 h2f[4] = { __half22float2(*(__half2*)&h2p.x),
                          __half22float2(*(__half2*)&h2p.y),
                          __half22float2(*(__half2*)&h2p.z),
                          __half22float2(*(__half2*)&h2p.w) };

        const float4* xp = (const float4*)x + row * 16 + flane * 2;
        float4 x0 = __ldg(&xp[0]);
        float4 x1 = __ldg(&xp[1]);

        float4 o0, o1;
        o0.x = 0.25f * (x0.x + h1f[0].x + h2f[0].x + a[0]);
        o0.y = 0.25f * (x0.y + h1f[0].y + h2f[0].y + a[1]);
        o0.z = 0.25f * (x0.z + h1f[1].x + h2f[1].x + a[2]);
        o0.w = 0.25f * (x0.w + h1f[1].y + h2f[1].y + a[3]);
        o1.x = 0.25f * (x1.x + h1f[2].x + h2f[2].x + a[4]);
        o1.y = 0.25f * (x1.y + h1f[2].y + h2f[2].y + a[5]);
        o1.z = 0.25f * (x1.z + h1f[3].x + h2f[3].x + a[6]);
        o1.w = 0.25f * (x1.w + h1f[3].y + h2f[3].y + a[7]);

        float4* op = (float4*)out + row * 16 + flane * 2;
        op[0] = o0;
        op[1] = o1;
    }
}

// ----------------------------------------------------------------------------
// launch (4 kernels total)
// ----------------------------------------------------------------------------
extern "C" void kernel_launch(void* const* d_in, const int* in_sizes, int n_in,
                              void* d_out, int out_size) {
    const float* x   = (const float*)d_in[0];
    const float* w   = (const float*)d_in[1];
    const int*   src = (const int*)d_in[2];
    const int*   dst = (const int*)d_in[3];
    float*       out = (float*)d_out;

    (void)in_sizes; (void)n_in; (void)out_size;

    __half* hA; __half* hB;
    cudaGetSymbolAddress((void**)&hA, g_h);
    cudaGetSymbolAddress((void**)&hB, g_t);

    // 1) fused prep: h = fp16(x), degree count, scan, CSR fill (1 launch)
    prep_kernel<<<PB, PT>>>((const float4*)x,
                            (const int4*)src, (const int4*)dst, (const float4*)w);

    // 2-4) hops. Ping-pong: g_h holds x -> hop1 writes h1 to g_t ->
    //      hop2 writes h2 to g_h -> hop3 gathers g_h, combines h1,h2,x -> out.
    dim3 blk(256);
    dim3 grd(148 * 6);                               // persistent: 6 blocks/SM
    spmm_mid_kernel<<<grd, blk>>>(hA, hB);           // hop 1: x  -> h1 (g_t)
    spmm_mid_kernel<<<grd, blk>>>(hB, hA);           // hop 2: h1 -> h2 (g_h)
    spmm_last_kernel<<<grd, blk>>>(hA, hB, x, out);  // hop 3 + final combine
}